// round 15
// baseline (speedup 1.0000x reference)
#include <cuda_runtime.h>
#include <cstdint>

#define BATCH 256
#define SEQ   64
#define DIMW  1024
#define SDIMW 256
#define MROWS (BATCH*SEQ)   // 16384
#define EPS   1e-5f

// ---------------- scratch (static device globals; no runtime allocation) ----
__device__ float g_decay[MROWS * SDIMW];
__device__ float g_drive[MROWS * SDIMW];
__device__ float g_hs   [MROWS * SDIMW];
__device__ float g_hidden[(size_t)MROWS * DIMW];  // layer-0 hidden (tf32-rounded)
__device__ float g_xr    [(size_t)MROWS * DIMW];  // tf32-rounded X
__device__ float g_final [BATCH * SDIMW];
__device__ float g_cstate[BATCH * DIMW];
__device__ float g_pooled[BATCH * DIMW];
__device__ float g_wt[6 * SDIMW * DIMW];   // transposed + tf32-rounded weights

__device__ __forceinline__ float softplusf(float x) {
    float e = __expf(-fabsf(x));
    return fmaxf(x, 0.f) + __logf(1.f + e);
}
__device__ __forceinline__ float tf32r(float f) {
    uint32_t r;
    asm("cvt.rna.tf32.f32 %0, %1;" : "=r"(r) : "f"(f));
    return __uint_as_float(r);
}
__device__ __forceinline__ float4 tf32r4(float4 v) {
    return make_float4(tf32r(v.x), tf32r(v.y), tf32r(v.z), tf32r(v.w));
}
__device__ __forceinline__ uint32_t smem_u32(const void* p) {
    uint32_t a;
    asm("{ .reg .u64 t; cvta.to.shared.u64 t, %1; cvt.u32.u64 %0, t; }"
        : "=r"(a) : "l"(p));
    return a;
}
__device__ __forceinline__ void ldm_x4(uint32_t addr, uint32_t* r) {
    asm volatile("ldmatrix.sync.aligned.m8n8.x4.shared.b16 {%0,%1,%2,%3}, [%4];"
                 : "=r"(r[0]), "=r"(r[1]), "=r"(r[2]), "=r"(r[3]) : "r"(addr));
}
__device__ __forceinline__ void mma8(float* c, const uint32_t* a, const uint32_t* b) {
    asm volatile("mma.sync.aligned.m16n8k8.row.col.f32.tf32.tf32.f32 "
                 "{%0,%1,%2,%3}, {%4,%5,%6,%7}, {%8,%9}, {%0,%1,%2,%3};"
                 : "+f"(c[0]), "+f"(c[1]), "+f"(c[2]), "+f"(c[3])
                 : "r"(a[0]), "r"(a[1]), "r"(a[2]), "r"(a[3]),
                   "r"(b[0]), "r"(b[1]));
}
__device__ __forceinline__ void cp16(uint32_t dst, const void* src) {
    asm volatile("cp.async.cg.shared.global [%0], [%1], 16;"
                 :: "r"(dst), "l"(src) : "memory");
}
__device__ __forceinline__ void cp_commit() {
    asm volatile("cp.async.commit_group;" ::: "memory");
}

// ---------------------------------------------------------------------------
// elementwise tf32 rounding (X -> Xr)
// ---------------------------------------------------------------------------
__global__ __launch_bounds__(256)
void round_kernel(const float4* __restrict__ in, float4* __restrict__ out) {
    const size_t i = (size_t)blockIdx.x * 256 + threadIdx.x;
    out[i] = tf32r4(in[i]);
}

// ---------------------------------------------------------------------------
// 6 weight transposes (+ tf32 round) in one launch.
// ---------------------------------------------------------------------------
__global__ void transpose6_kernel(const float* __restrict__ Wd,
                                  const float* __restrict__ Wi,
                                  const float* __restrict__ Wo,
                                  float* __restrict__ wt) {
    __shared__ float t[32][33];
    const int z = blockIdx.z;
    const int layer = z / 3, mat = z % 3;
    const size_t WSZ = (size_t)SDIMW * DIMW;
    const float* src = (mat == 0 ? Wd : (mat == 1 ? Wi : Wo)) + layer * WSZ;
    float* dst = wt + (size_t)z * WSZ;
    int R, C, c0, r0;
    if (mat == 2) { R = SDIMW; C = DIMW; c0 = blockIdx.y * 32; r0 = blockIdx.x * 32; }
    else          { R = DIMW; C = SDIMW; c0 = blockIdx.x * 32; r0 = blockIdx.y * 32; }
    const int tx = threadIdx.x, ty = threadIdx.y;
    #pragma unroll
    for (int k = 0; k < 4; k++)
        t[ty + 8 * k][tx] = src[(size_t)(r0 + ty + 8 * k) * C + c0 + tx];
    __syncthreads();
    #pragma unroll
    for (int k = 0; k < 4; k++)
        dst[(size_t)(c0 + ty + 8 * k) * R + r0 + tx] = tf32r(t[tx][ty + 8 * k]);
}

// ---------------------------------------------------------------------------
// proj v2: 512 threads, 16 warps (4m x 4n), warp tile 32m x 16n dual.
// cp.async 3-stage. Same smem layout; per-element accumulation order
// unchanged -> bit-identical to R13.
// smem: A @ s*16384 (3x16KB), Bd @49152+s*8192, Bi @73728+s*8192, biases @98304.
// ---------------------------------------------------------------------------
#define PJ_SMEM (98304 + 3 * 64 * 4)
__global__ __launch_bounds__(512)
void proj_mma_kernel(const float* __restrict__ X,
                     const float* __restrict__ WdT, const float* __restrict__ WiT,
                     const float* __restrict__ bd, const float* __restrict__ bi,
                     const float* __restrict__ A_log,
                     float* __restrict__ decay, float* __restrict__ drive)
{
    extern __shared__ char smem[];
    const uint32_t sbase = smem_u32(smem);
    const int tid = threadIdx.x, wid = tid >> 5, lane = tid & 31;
    const int wm = wid & 3, wn = wid >> 2;     // 4 x 4 warp grid
    const int m0 = blockIdx.y * 128, n0 = blockIdx.x * 64;

    float* sbd = (float*)(smem + 98304);
    float* sbi = sbd + 64;
    float* ssa = sbi + 64;
    if (tid < 64) {
        sbd[tid] = bd[n0 + tid];
        sbi[tid] = bi[n0 + tid];
        ssa[tid] = softplusf(A_log[n0 + tid]);
    }

    const int lrow4 = tid >> 3, lc16 = tid & 7;   // lrow4: 0..63
    const int swz = lane & 7, sel = lane >> 3;
    const int selr = (sel & 1) * 8, selc = sel >> 1;

    uint32_t aRow[2], bRow[2];
    #pragma unroll
    for (int mt = 0; mt < 2; mt++)
        aRow[mt] = (uint32_t)((wm * 32 + mt * 16 + selr + swz) * 128);
    #pragma unroll
    for (int nt = 0; nt < 2; nt++)
        bRow[nt] = (uint32_t)((wn * 16 + nt * 8 + swz) * 128);

    const uint32_t ldOffA[2] = {
        (uint32_t)((lrow4 + 0)  * 128 + ((lc16 ^ ((lrow4 + 0)  & 7)) << 4)),
        (uint32_t)((lrow4 + 64) * 128 + ((lc16 ^ ((lrow4 + 64) & 7)) << 4))
    };
    const float* aSrc = X   + (size_t)(m0 + lrow4) * DIMW + lc16 * 4;
    const float* dSrc = WdT + (size_t)(n0 + lrow4) * DIMW + lc16 * 4;
    const float* iSrc = WiT + (size_t)(n0 + lrow4) * DIMW + lc16 * 4;

    #define PJ_ISSUE(kt_) do {                                                  \
        const int _s = (kt_) % 3;                                               \
        const int _k0 = (kt_) * 32;                                             \
        _Pragma("unroll")                                                       \
        for (int i = 0; i < 2; i++)                                             \
            cp16(sbase + _s * 16384 + ldOffA[i],                                \
                 aSrc + (size_t)(i * 64) * DIMW + _k0);                         \
        cp16(sbase + 49152 + _s * 8192 + ldOffA[0], dSrc + _k0);                \
        cp16(sbase + 73728 + _s * 8192 + ldOffA[0], iSrc + _k0);                \
        cp_commit();                                                            \
    } while (0)

    PJ_ISSUE(0);
    PJ_ISSUE(1);

    float accD[2][2][4] = {};
    float accI[2][2][4] = {};

    const int KT = DIMW / 32;   // 32
    for (int kt = 0; kt < KT; kt++) {
        if (kt == KT - 1)
            asm volatile("cp.async.wait_group 0;" ::: "memory");
        else
            asm volatile("cp.async.wait_group 1;" ::: "memory");
        __syncthreads();
        if (kt + 2 < KT) PJ_ISSUE(kt + 2);

        const uint32_t Asm  = sbase + (kt % 3) * 16384;
        const uint32_t Bdsm = sbase + 49152 + (kt % 3) * 8192;
        const uint32_t Bism = sbase + 73728 + (kt % 3) * 8192;

        uint32_t af[2][4][4];
        #pragma unroll
        for (int mt = 0; mt < 2; mt++)
            #pragma unroll
            for (int kk = 0; kk < 4; kk++)
                ldm_x4(Asm + aRow[mt] + (((kk * 2 + selc) ^ swz) << 4), af[mt][kk]);

        #pragma unroll
        for (int out = 0; out < 2; out++) {
            const uint32_t Bsm = out ? Bism : Bdsm;
            #pragma unroll
            for (int kh = 0; kh < 2; kh++) {
                uint32_t bf[2][4];
                #pragma unroll
                for (int nt = 0; nt < 2; nt++)
                    ldm_x4(Bsm + bRow[nt] + (((kh * 4 + sel) ^ swz) << 4), bf[nt]);
                #pragma unroll
                for (int kk2 = 0; kk2 < 2; kk2++)
                    #pragma unroll
                    for (int mt = 0; mt < 2; mt++)
                        #pragma unroll
                        for (int nt = 0; nt < 2; nt++)
                            mma8(out ? accI[mt][nt] : accD[mt][nt],
                                 af[mt][kh * 2 + kk2], &bf[nt][kk2 * 2]);
            }
        }
    }

    const int g = lane >> 2, t = lane & 3;
    #pragma unroll
    for (int mt = 0; mt < 2; mt++) {
        const int row0 = m0 + wm * 32 + mt * 16 + g;
        #pragma unroll
        for (int nt = 0; nt < 2; nt++) {
            const int nl = wn * 16 + nt * 8 + 2 * t;
            const float b0 = sbd[nl], b1 = sbd[nl + 1];
            const float i0 = sbi[nl], i1 = sbi[nl + 1];
            const float a0 = ssa[nl], a1 = ssa[nl + 1];
            #pragma unroll
            for (int rh = 0; rh < 2; rh++) {
                const int row = row0 + rh * 8;
                const float de0 = softplusf(accD[mt][nt][rh * 2 + 0] + b0);
                const float de1 = softplusf(accD[mt][nt][rh * 2 + 1] + b1);
                float2 dec = make_float2(__expf(-de0 * a0), __expf(-de1 * a1));
                float2 drv = make_float2(de0 * (accI[mt][nt][rh * 2 + 0] + i0),
                                         de1 * (accI[mt][nt][rh * 2 + 1] + i1));
                *(float2*)(decay + (size_t)row * SDIMW + n0 + nl) = dec;
                *(float2*)(drive + (size_t)row * SDIMW + n0 + nl) = drv;
            }
        }
    }
}

// ---------------------------------------------------------------------------
// outgemm v2 (R13-proven): CTA 128m x 64n, warp 64m x 16n, 2 CTAs/SM.
// ---------------------------------------------------------------------------
#define OG_SMEM (73728 + 64 * 4)
__global__ __launch_bounds__(256, 2)
void outgemm_mma_kernel(const float* __restrict__ HS, const float* __restrict__ WoT,
                        const float* __restrict__ bo, const float* __restrict__ cs,
                        float* __restrict__ out, float* __restrict__ pooled,
                        int roundOut)
{
    extern __shared__ char smem[];
    const uint32_t sbase = smem_u32(smem);
    const int tid = threadIdx.x, wid = tid >> 5, lane = tid & 31;
    const int wm = wid & 1, wn = wid >> 1;
    const int m0 = blockIdx.y * 128, n0 = blockIdx.x * 64;

    float* sbo = (float*)(smem + 73728);
    if (tid < 64) sbo[tid] = bo[n0 + tid];

    const int lrow4 = tid >> 3, lc16 = tid & 7;
    const int swz = lane & 7, sel = lane >> 3;
    const int selr = (sel & 1) * 8, selc = sel >> 1;

    uint32_t aRow[4], bRow[2];
    #pragma unroll
    for (int mt = 0; mt < 4; mt++)
        aRow[mt] = (uint32_t)((wm * 64 + mt * 16 + selr + swz) * 128);
    #pragma unroll
    for (int nt = 0; nt < 2; nt++)
        bRow[nt] = (uint32_t)((wn * 16 + nt * 8 + swz) * 128);

    const uint32_t ldOff[4] = {
        (uint32_t)((lrow4 + 0)  * 128 + ((lc16 ^ ((lrow4 + 0)  & 7)) << 4)),
        (uint32_t)((lrow4 + 32) * 128 + ((lc16 ^ ((lrow4 + 32) & 7)) << 4)),
        (uint32_t)((lrow4 + 64) * 128 + ((lc16 ^ ((lrow4 + 64) & 7)) << 4)),
        (uint32_t)((lrow4 + 96) * 128 + ((lc16 ^ ((lrow4 + 96) & 7)) << 4))
    };
    const float* aSrc = HS  + (size_t)(m0 + lrow4) * SDIMW + lc16 * 4;
    const float* bSrc = WoT + (size_t)(n0 + lrow4) * SDIMW + lc16 * 4;

    #define OG_ISSUE(kt_) do {                                                  \
        const int _s = (kt_) % 3;                                               \
        const int _k0 = (kt_) * 32;                                             \
        _Pragma("unroll")                                                       \
        for (int i = 0; i < 4; i++)                                             \
            cp16(sbase + _s * 16384 + ldOff[i],                                 \
                 aSrc + (size_t)(i * 32) * SDIMW + _k0);                        \
        _Pragma("unroll")                                                       \
        for (int i = 0; i < 2; i++)                                             \
            cp16(sbase + 49152 + _s * 8192 + ldOff[i],                          \
                 bSrc + (size_t)(i * 32) * SDIMW + _k0);                        \
        cp_commit();                                                            \
    } while (0)

    OG_ISSUE(0);
    OG_ISSUE(1);

    float acc[4][2][4] = {};

    const int KT = SDIMW / 32;   // 8
    for (int kt = 0; kt < KT; kt++) {
        if (kt == KT - 1)
            asm volatile("cp.async.wait_group 0;" ::: "memory");
        else
            asm volatile("cp.async.wait_group 1;" ::: "memory");
        __syncthreads();
        if (kt + 2 < KT) OG_ISSUE(kt + 2);

        const uint32_t Asm = sbase + (kt % 3) * 16384;
        const uint32_t Bsm = sbase + 49152 + (kt % 3) * 8192;

        #pragma unroll
        for (int kh = 0; kh < 2; kh++) {
            uint32_t bf[2][4];
            #pragma unroll
            for (int nt = 0; nt < 2; nt++)
                ldm_x4(Bsm + bRow[nt] + (((kh * 4 + sel) ^ swz) << 4), bf[nt]);
            #pragma unroll
            for (int kk2 = 0; kk2 < 2; kk2++) {
                const int kk = kh * 2 + kk2;
                uint32_t af[4][4];
                #pragma unroll
                for (int mt = 0; mt < 4; mt++)
                    ldm_x4(Asm + aRow[mt] + (((kk * 2 + selc) ^ swz) << 4), af[mt]);
                #pragma unroll
                for (int mt = 0; mt < 4; mt++)
                    #pragma unroll
                    for (int nt = 0; nt < 2; nt++)
                        mma8(acc[mt][nt], af[mt], &bf[nt][kk2 * 2]);
            }
        }
    }

    const int g = lane >> 2, t = lane & 3;
    const int bb = blockIdx.y * 2 + wm;
    float psum[2][2];
    #pragma unroll
    for (int nt = 0; nt < 2; nt++) {
        const int nl = wn * 16 + nt * 8 + 2 * t;
        const float2 cv = *(const float2*)(cs + (size_t)bb * DIMW + n0 + nl);
        const float add0 = sbo[nl] + cv.x;
        const float add1 = sbo[nl + 1] + cv.y;
        float s0 = 0.f, s1 = 0.f;
        #pragma unroll
        for (int mt = 0; mt < 4; mt++) {
            const int row0 = m0 + wm * 64 + mt * 16 + g;
            #pragma unroll
            for (int rh = 0; rh < 2; rh++) {
                const int row = row0 + rh * 8;
                float2 ov = make_float2(acc[mt][nt][rh * 2 + 0] + add0,
                                        acc[mt][nt][rh * 2 + 1] + add1);
                if (roundOut) { ov.x = tf32r(ov.x); ov.y = tf32r(ov.y); }
                *(float2*)(out + (size_t)row * DIMW + n0 + nl) = ov;
                s0 += ov.x; s1 += ov.y;
            }
        }
        psum[nt][0] = s0; psum[nt][1] = s1;
    }
    if (pooled) {
        #pragma unroll
        for (int nt = 0; nt < 2; nt++) {
            #pragma unroll
            for (int o = 4; o < 32; o <<= 1) {
                psum[nt][0] += __shfl_xor_sync(0xffffffffu, psum[nt][0], o);
                psum[nt][1] += __shfl_xor_sync(0xffffffffu, psum[nt][1], o);
            }
        }
        if (lane < 4) {
            #pragma unroll
            for (int nt = 0; nt < 2; nt++) {
                const int nl = wn * 16 + nt * 8 + 2 * lane;
                float2 pv = make_float2(psum[nt][0] * (1.f / (float)SEQ),
                                        psum[nt][1] * (1.f / (float)SEQ));
                *(float2*)(pooled + (size_t)bb * DIMW + n0 + nl) = pv;
            }
        }
    }
}

// ---------------------------------------------------------------------------
__global__ __launch_bounds__(256)
void scan_kernel(const float* __restrict__ decay, const float* __restrict__ drive,
                 float* __restrict__ hs, float* __restrict__ fin)
{
    const int b = blockIdx.x;
    const int n = threadIdx.x;
    size_t base = (size_t)b * SEQ * SDIMW + n;
    float h = 0.f;
    #pragma unroll 8
    for (int s = 0; s < SEQ; s++) {
        size_t idx = base + (size_t)s * SDIMW;
        h = fmaf(decay[idx], h, drive[idx]);
        hs[idx] = tf32r(h);
    }
    fin[b * SDIMW + n] = h;
}

// ---------------------------------------------------------------------------
// cstate v3 (R12-proven): 256 thr, CS_BG=4, n unrolled x8.
// ---------------------------------------------------------------------------
#define CS_BG 4
__global__ __launch_bounds__(256)
void cstate_kernel(const float* __restrict__ fin, const float* __restrict__ Ws,
                   const float* __restrict__ bs, float* __restrict__ cs)
{
    __shared__ float sf[CS_BG][SDIMW];
    const int d = blockIdx.x * 256 + threadIdx.x;
    const int b0 = blockIdx.y * CS_BG;
    {
        const int row = threadIdx.x >> 6, c4 = threadIdx.x & 63;
        *(float4*)&sf[row][c4 * 4] =
            *(const float4*)(fin + (size_t)(b0 + row) * SDIMW + c4 * 4);
    }
    __syncthreads();

    float acc[CS_BG] = {};
    #pragma unroll 4
    for (int n = 0; n < SDIMW; n += 8) {
        float w[8];
        #pragma unroll
        for (int j = 0; j < 8; j++)
            w[j] = Ws[(size_t)(n + j) * DIMW + d];
        #pragma unroll
        for (int b = 0; b < CS_BG; b++) {
            #pragma unroll
            for (int j = 0; j < 8; j++)
                acc[b] = fmaf(sf[b][n + j], w[j], acc[b]);
        }
    }
    const float bsv = bs[d];
    #pragma unroll
    for (int b = 0; b < CS_BG; b++)
        cs[(size_t)(b0 + b) * DIMW + d] = acc[b] + bsv;
}

// ---------------------------------------------------------------------------
__global__ __launch_bounds__(256)
void final_kernel(const float* __restrict__ pmean, const float* __restrict__ cs,
                  const float* __restrict__ gamma, const float* __restrict__ beta,
                  float* __restrict__ out)
{
    const int b = blockIdx.x;
    const int tid = threadIdx.x;

    float pooled[4];
    float lsum = 0.f, lsq = 0.f;
    #pragma unroll
    for (int i = 0; i < 4; i++) {
        const int d = i * 256 + tid;
        float p = cs[(size_t)b * DIMW + d] + pmean[(size_t)b * DIMW + d];
        pooled[i] = p;
        lsum += p;
        lsq  += p * p;
    }

    __shared__ float s1[8], s2[8];
    #pragma unroll
    for (int o = 16; o > 0; o >>= 1) {
        lsum += __shfl_xor_sync(0xffffffffu, lsum, o);
        lsq  += __shfl_xor_sync(0xffffffffu, lsq,  o);
    }
    if ((tid & 31) == 0) { s1[tid >> 5] = lsum; s2[tid >> 5] = lsq; }
    __syncthreads();
    float tsum = 0.f, tsq = 0.f;
    #pragma unroll
    for (int w = 0; w < 8; w++) { tsum += s1[w]; tsq += s2[w]; }

    const float mu  = tsum * (1.f / (float)DIMW);
    const float var = tsq * (1.f / (float)DIMW) - mu * mu;
    const float rstd = rsqrtf(var + EPS);

    #pragma unroll
    for (int i = 0; i < 4; i++) {
        const int d = i * 256 + tid;
        out[(size_t)b * DIMW + d] = (pooled[i] - mu) * rstd * gamma[d] + beta[d];
    }
}

// ---------------------------------------------------------------------------
extern "C" void kernel_launch(void* const* d_in, const int* in_sizes, int n_in,
                              void* d_out, int out_size)
{
    const float* X     = (const float*)d_in[0];
    const float* Wd    = (const float*)d_in[1];
    const float* bd    = (const float*)d_in[2];
    const float* Wi    = (const float*)d_in[3];
    const float* bi    = (const float*)d_in[4];
    const float* A_log = (const float*)d_in[5];
    const float* Wo    = (const float*)d_in[6];
    const float* bo    = (const float*)d_in[7];
    const float* Ws    = (const float*)d_in[8];
    const float* bs    = (const float*)d_in[9];
    const float* gamma = (const float*)d_in[10];
    const float* beta  = (const float*)d_in[11];

    float* out_repr   = (float*)d_out;                         // [B, D]
    float* out_hidden = (float*)d_out + (size_t)BATCH * DIMW;  // [B, S, D]

    float *p_decay, *p_drive, *p_hs, *p_hidden, *p_xr, *p_final, *p_cstate,
          *p_pooled, *p_wt;
    cudaGetSymbolAddress((void**)&p_decay,  g_decay);
    cudaGetSymbolAddress((void**)&p_drive,  g_drive);
    cudaGetSymbolAddress((void**)&p_hs,     g_hs);
    cudaGetSymbolAddress((void**)&p_hidden, g_hidden);
    cudaGetSymbolAddress((void**)&p_xr,     g_xr);
    cudaGetSymbolAddress((void**)&p_final,  g_final);
    cudaGetSymbolAddress((void**)&p_cstate, g_cstate);
    cudaGetSymbolAddress((void**)&p_pooled, g_pooled);
    cudaGetSymbolAddress((void**)&p_wt,     g_wt);

    cudaFuncSetAttribute(proj_mma_kernel,
                         cudaFuncAttributeMaxDynamicSharedMemorySize, PJ_SMEM);
    cudaFuncSetAttribute(outgemm_mma_kernel,
                         cudaFuncAttributeMaxDynamicSharedMemorySize, OG_SMEM);

    const size_t WSZ = (size_t)SDIMW * DIMW;
    float* WdT0 = p_wt + 0 * WSZ;
    float* WiT0 = p_wt + 1 * WSZ;
    float* WoT0 = p_wt + 2 * WSZ;
    float* WdT1 = p_wt + 3 * WSZ;
    float* WiT1 = p_wt + 4 * WSZ;
    float* WoT1 = p_wt + 5 * WSZ;

    transpose6_kernel<<<dim3(8, 32, 6), dim3(32, 8)>>>(Wd, Wi, Wo, p_wt);
    round_kernel<<<(MROWS * DIMW) / (256 * 4), 256>>>((const float4*)X,
                                                      (float4*)p_xr);

    const dim3 pjGrid(SDIMW / 64, MROWS / 128);    // (4, 128)
    const dim3 ogGrid(DIMW / 64, MROWS / 128);     // (16, 128)
    const dim3 csGrid(DIMW / 256, BATCH / CS_BG);  // (4, 64)

    // ---------------- layer 0 ----------------
    proj_mma_kernel<<<pjGrid, 512, PJ_SMEM>>>(p_xr, WdT0, WiT0, bd, bi, A_log,
                                              p_decay, p_drive);
    scan_kernel<<<BATCH, 256>>>(p_decay, p_drive, p_hs, p_final);
    cstate_kernel<<<csGrid, 256>>>(p_final, Ws, bs, p_cstate);
    outgemm_mma_kernel<<<ogGrid, 256, OG_SMEM>>>(p_hs, WoT0, bo, p_cstate,
                                                 p_hidden, nullptr, 1);

    // ---------------- layer 1 (hidden already tf32-rounded) ----------------
    proj_mma_kernel<<<pjGrid, 512, PJ_SMEM>>>(p_hidden, WdT1, WiT1, bd + SDIMW,
                                              bi + SDIMW, A_log + SDIMW,
                                              p_decay, p_drive);
    scan_kernel<<<BATCH, 256>>>(p_decay, p_drive, p_hs, p_final);
    cstate_kernel<<<csGrid, 256>>>(p_final, Ws + WSZ, bs + DIMW, p_cstate);
    outgemm_mma_kernel<<<ogGrid, 256, OG_SMEM>>>(p_hs, WoT1, bo + DIMW, p_cstate,
                                                 out_hidden, p_pooled, 0);

    // ---------------- LayerNorm ----------------
    final_kernel<<<BATCH, 256>>>(p_pooled, p_cstate, gamma, beta, out_repr);
}

// round 16
// speedup vs baseline: 1.1579x; 1.1579x over previous
#include <cuda_runtime.h>
#include <cstdint>

#define BATCH 256
#define SEQ   64
#define DIMW  1024
#define SDIMW 256
#define MROWS (BATCH*SEQ)   // 16384
#define EPS   1e-5f

// ---------------- scratch (static device globals; no runtime allocation) ----
__device__ float g_decay[MROWS * SDIMW];
__device__ float g_drive[MROWS * SDIMW];
__device__ float g_hs   [MROWS * SDIMW];
__device__ float g_hidden[(size_t)MROWS * DIMW];  // layer-0 hidden (tf32-rounded)
__device__ float g_xr    [(size_t)MROWS * DIMW];  // tf32-rounded X
__device__ float g_final [BATCH * SDIMW];
__device__ float g_cstate[BATCH * DIMW];
__device__ float g_pooled[BATCH * DIMW];
__device__ float g_wt[6 * SDIMW * DIMW];   // transposed + tf32-rounded weights

__device__ __forceinline__ float softplusf(float x) {
    float e = __expf(-fabsf(x));
    return fmaxf(x, 0.f) + __logf(1.f + e);
}
__device__ __forceinline__ float tf32r(float f) {
    uint32_t r;
    asm("cvt.rna.tf32.f32 %0, %1;" : "=r"(r) : "f"(f));
    return __uint_as_float(r);
}
__device__ __forceinline__ float4 tf32r4(float4 v) {
    return make_float4(tf32r(v.x), tf32r(v.y), tf32r(v.z), tf32r(v.w));
}
__device__ __forceinline__ uint32_t smem_u32(const void* p) {
    uint32_t a;
    asm("{ .reg .u64 t; cvta.to.shared.u64 t, %1; cvt.u32.u64 %0, t; }"
        : "=r"(a) : "l"(p));
    return a;
}
__device__ __forceinline__ void ldm_x4(uint32_t addr, uint32_t* r) {
    asm volatile("ldmatrix.sync.aligned.m8n8.x4.shared.b16 {%0,%1,%2,%3}, [%4];"
                 : "=r"(r[0]), "=r"(r[1]), "=r"(r[2]), "=r"(r[3]) : "r"(addr));
}
__device__ __forceinline__ void mma8(float* c, const uint32_t* a, const uint32_t* b) {
    asm volatile("mma.sync.aligned.m16n8k8.row.col.f32.tf32.tf32.f32 "
                 "{%0,%1,%2,%3}, {%4,%5,%6,%7}, {%8,%9}, {%0,%1,%2,%3};"
                 : "+f"(c[0]), "+f"(c[1]), "+f"(c[2]), "+f"(c[3])
                 : "r"(a[0]), "r"(a[1]), "r"(a[2]), "r"(a[3]),
                   "r"(b[0]), "r"(b[1]));
}
__device__ __forceinline__ void cp16(uint32_t dst, const void* src) {
    asm volatile("cp.async.cg.shared.global [%0], [%1], 16;"
                 :: "r"(dst), "l"(src) : "memory");
}
__device__ __forceinline__ void cp_commit() {
    asm volatile("cp.async.commit_group;" ::: "memory");
}

// ---------------------------------------------------------------------------
// elementwise tf32 rounding (X -> Xr)
// ---------------------------------------------------------------------------
__global__ __launch_bounds__(256)
void round_kernel(const float4* __restrict__ in, float4* __restrict__ out) {
    const size_t i = (size_t)blockIdx.x * 256 + threadIdx.x;
    out[i] = tf32r4(in[i]);
}

// ---------------------------------------------------------------------------
// 6 weight transposes (+ tf32 round) in one launch.
// ---------------------------------------------------------------------------
__global__ void transpose6_kernel(const float* __restrict__ Wd,
                                  const float* __restrict__ Wi,
                                  const float* __restrict__ Wo,
                                  float* __restrict__ wt) {
    __shared__ float t[32][33];
    const int z = blockIdx.z;
    const int layer = z / 3, mat = z % 3;
    const size_t WSZ = (size_t)SDIMW * DIMW;
    const float* src = (mat == 0 ? Wd : (mat == 1 ? Wi : Wo)) + layer * WSZ;
    float* dst = wt + (size_t)z * WSZ;
    int R, C, c0, r0;
    if (mat == 2) { R = SDIMW; C = DIMW; c0 = blockIdx.y * 32; r0 = blockIdx.x * 32; }
    else          { R = DIMW; C = SDIMW; c0 = blockIdx.x * 32; r0 = blockIdx.y * 32; }
    const int tx = threadIdx.x, ty = threadIdx.y;
    #pragma unroll
    for (int k = 0; k < 4; k++)
        t[ty + 8 * k][tx] = src[(size_t)(r0 + ty + 8 * k) * C + c0 + tx];
    __syncthreads();
    #pragma unroll
    for (int k = 0; k < 4; k++)
        dst[(size_t)(c0 + ty + 8 * k) * R + r0 + tx] = tf32r(t[tx][ty + 8 * k]);
}

// ---------------------------------------------------------------------------
// proj v3: CTA 128m x 32n(dual), 8 warps 4m x 2n, warp tile 32m x 16n dual.
// 2 CTAs/SM (smem 72KB, launch_bounds(256,2)). cp.async 3-stage.
// Per-element k-accumulation order identical to R13 -> bit-identical output.
// smem: A @ s*16384 (3x16KB), Bd @49152+s*4096, Bi @61440+s*4096, biases @73728.
// ---------------------------------------------------------------------------
#define PJ_SMEM (73728 + 3 * 32 * 4)
__global__ __launch_bounds__(256, 2)
void proj_mma_kernel(const float* __restrict__ X,
                     const float* __restrict__ WdT, const float* __restrict__ WiT,
                     const float* __restrict__ bd, const float* __restrict__ bi,
                     const float* __restrict__ A_log,
                     float* __restrict__ decay, float* __restrict__ drive)
{
    extern __shared__ char smem[];
    const uint32_t sbase = smem_u32(smem);
    const int tid = threadIdx.x, wid = tid >> 5, lane = tid & 31;
    const int wm = wid & 3, wn = wid >> 2;     // 4m x 2n warp grid
    const int m0 = blockIdx.y * 128, n0 = blockIdx.x * 32;

    float* sbd = (float*)(smem + 73728);
    float* sbi = sbd + 32;
    float* ssa = sbi + 32;
    if (tid < 32) {
        sbd[tid] = bd[n0 + tid];
        sbi[tid] = bi[n0 + tid];
        ssa[tid] = softplusf(A_log[n0 + tid]);
    }

    const int lrow4 = tid >> 3, lc16 = tid & 7;   // lrow4: 0..31
    const int swz = lane & 7, sel = lane >> 3;
    const int selr = (sel & 1) * 8, selc = sel >> 1;

    uint32_t aRow[2], bRow[2];
    #pragma unroll
    for (int mt = 0; mt < 2; mt++)
        aRow[mt] = (uint32_t)((wm * 32 + mt * 16 + selr + swz) * 128);
    #pragma unroll
    for (int nt = 0; nt < 2; nt++)
        bRow[nt] = (uint32_t)((wn * 16 + nt * 8 + swz) * 128);

    const uint32_t ldOffA[4] = {
        (uint32_t)((lrow4 + 0)  * 128 + ((lc16 ^ ((lrow4 + 0)  & 7)) << 4)),
        (uint32_t)((lrow4 + 32) * 128 + ((lc16 ^ ((lrow4 + 32) & 7)) << 4)),
        (uint32_t)((lrow4 + 64) * 128 + ((lc16 ^ ((lrow4 + 64) & 7)) << 4)),
        (uint32_t)((lrow4 + 96) * 128 + ((lc16 ^ ((lrow4 + 96) & 7)) << 4))
    };
    const float* aSrc = X   + (size_t)(m0 + lrow4) * DIMW + lc16 * 4;
    const float* dSrc = WdT + (size_t)(n0 + lrow4) * DIMW + lc16 * 4;
    const float* iSrc = WiT + (size_t)(n0 + lrow4) * DIMW + lc16 * 4;

    #define PJ_ISSUE(kt_) do {                                                  \
        const int _s = (kt_) % 3;                                               \
        const int _k0 = (kt_) * 32;                                             \
        _Pragma("unroll")                                                       \
        for (int i = 0; i < 4; i++)                                             \
            cp16(sbase + _s * 16384 + ldOffA[i],                                \
                 aSrc + (size_t)(i * 32) * DIMW + _k0);                         \
        cp16(sbase + 49152 + _s * 4096 + ldOffA[0], dSrc + _k0);                \
        cp16(sbase + 61440 + _s * 4096 + ldOffA[0], iSrc + _k0);                \
        cp_commit();                                                            \
    } while (0)

    PJ_ISSUE(0);
    PJ_ISSUE(1);

    float accD[2][2][4] = {};
    float accI[2][2][4] = {};

    const int KT = DIMW / 32;   // 32
    for (int kt = 0; kt < KT; kt++) {
        if (kt == KT - 1)
            asm volatile("cp.async.wait_group 0;" ::: "memory");
        else
            asm volatile("cp.async.wait_group 1;" ::: "memory");
        __syncthreads();
        if (kt + 2 < KT) PJ_ISSUE(kt + 2);

        const uint32_t Asm  = sbase + (kt % 3) * 16384;
        const uint32_t Bdsm = sbase + 49152 + (kt % 3) * 4096;
        const uint32_t Bism = sbase + 61440 + (kt % 3) * 4096;

        uint32_t af[2][4][4];
        #pragma unroll
        for (int mt = 0; mt < 2; mt++)
            #pragma unroll
            for (int kk = 0; kk < 4; kk++)
                ldm_x4(Asm + aRow[mt] + (((kk * 2 + selc) ^ swz) << 4), af[mt][kk]);

        #pragma unroll
        for (int out = 0; out < 2; out++) {
            const uint32_t Bsm = out ? Bism : Bdsm;
            #pragma unroll
            for (int kh = 0; kh < 2; kh++) {
                uint32_t bf[2][4];
                #pragma unroll
                for (int nt = 0; nt < 2; nt++)
                    ldm_x4(Bsm + bRow[nt] + (((kh * 4 + sel) ^ swz) << 4), bf[nt]);
                #pragma unroll
                for (int kk2 = 0; kk2 < 2; kk2++)
                    #pragma unroll
                    for (int mt = 0; mt < 2; mt++)
                        #pragma unroll
                        for (int nt = 0; nt < 2; nt++)
                            mma8(out ? accI[mt][nt] : accD[mt][nt],
                                 af[mt][kh * 2 + kk2], &bf[nt][kk2 * 2]);
            }
        }
    }

    const int g = lane >> 2, t = lane & 3;
    #pragma unroll
    for (int mt = 0; mt < 2; mt++) {
        const int row0 = m0 + wm * 32 + mt * 16 + g;
        #pragma unroll
        for (int nt = 0; nt < 2; nt++) {
            const int nl = wn * 16 + nt * 8 + 2 * t;
            const float b0 = sbd[nl], b1 = sbd[nl + 1];
            const float i0 = sbi[nl], i1 = sbi[nl + 1];
            const float a0 = ssa[nl], a1 = ssa[nl + 1];
            #pragma unroll
            for (int rh = 0; rh < 2; rh++) {
                const int row = row0 + rh * 8;
                const float de0 = softplusf(accD[mt][nt][rh * 2 + 0] + b0);
                const float de1 = softplusf(accD[mt][nt][rh * 2 + 1] + b1);
                float2 dec = make_float2(__expf(-de0 * a0), __expf(-de1 * a1));
                float2 drv = make_float2(de0 * (accI[mt][nt][rh * 2 + 0] + i0),
                                         de1 * (accI[mt][nt][rh * 2 + 1] + i1));
                *(float2*)(decay + (size_t)row * SDIMW + n0 + nl) = dec;
                *(float2*)(drive + (size_t)row * SDIMW + n0 + nl) = drv;
            }
        }
    }
}

// ---------------------------------------------------------------------------
// outgemm v2 (R13-proven): CTA 128m x 64n, warp 64m x 16n, 2 CTAs/SM.
// ---------------------------------------------------------------------------
#define OG_SMEM (73728 + 64 * 4)
__global__ __launch_bounds__(256, 2)
void outgemm_mma_kernel(const float* __restrict__ HS, const float* __restrict__ WoT,
                        const float* __restrict__ bo, const float* __restrict__ cs,
                        float* __restrict__ out, float* __restrict__ pooled,
                        int roundOut)
{
    extern __shared__ char smem[];
    const uint32_t sbase = smem_u32(smem);
    const int tid = threadIdx.x, wid = tid >> 5, lane = tid & 31;
    const int wm = wid & 1, wn = wid >> 1;
    const int m0 = blockIdx.y * 128, n0 = blockIdx.x * 64;

    float* sbo = (float*)(smem + 73728);
    if (tid < 64) sbo[tid] = bo[n0 + tid];

    const int lrow4 = tid >> 3, lc16 = tid & 7;
    const int swz = lane & 7, sel = lane >> 3;
    const int selr = (sel & 1) * 8, selc = sel >> 1;

    uint32_t aRow[4], bRow[2];
    #pragma unroll
    for (int mt = 0; mt < 4; mt++)
        aRow[mt] = (uint32_t)((wm * 64 + mt * 16 + selr + swz) * 128);
    #pragma unroll
    for (int nt = 0; nt < 2; nt++)
        bRow[nt] = (uint32_t)((wn * 16 + nt * 8 + swz) * 128);

    const uint32_t ldOff[4] = {
        (uint32_t)((lrow4 + 0)  * 128 + ((lc16 ^ ((lrow4 + 0)  & 7)) << 4)),
        (uint32_t)((lrow4 + 32) * 128 + ((lc16 ^ ((lrow4 + 32) & 7)) << 4)),
        (uint32_t)((lrow4 + 64) * 128 + ((lc16 ^ ((lrow4 + 64) & 7)) << 4)),
        (uint32_t)((lrow4 + 96) * 128 + ((lc16 ^ ((lrow4 + 96) & 7)) << 4))
    };
    const float* aSrc = HS  + (size_t)(m0 + lrow4) * SDIMW + lc16 * 4;
    const float* bSrc = WoT + (size_t)(n0 + lrow4) * SDIMW + lc16 * 4;

    #define OG_ISSUE(kt_) do {                                                  \
        const int _s = (kt_) % 3;                                               \
        const int _k0 = (kt_) * 32;                                             \
        _Pragma("unroll")                                                       \
        for (int i = 0; i < 4; i++)                                             \
            cp16(sbase + _s * 16384 + ldOff[i],                                 \
                 aSrc + (size_t)(i * 32) * SDIMW + _k0);                        \
        _Pragma("unroll")                                                       \
        for (int i = 0; i < 2; i++)                                             \
            cp16(sbase + 49152 + _s * 8192 + ldOff[i],                          \
                 bSrc + (size_t)(i * 32) * SDIMW + _k0);                        \
        cp_commit();                                                            \
    } while (0)

    OG_ISSUE(0);
    OG_ISSUE(1);

    float acc[4][2][4] = {};

    const int KT = SDIMW / 32;   // 8
    for (int kt = 0; kt < KT; kt++) {
        if (kt == KT - 1)
            asm volatile("cp.async.wait_group 0;" ::: "memory");
        else
            asm volatile("cp.async.wait_group 1;" ::: "memory");
        __syncthreads();
        if (kt + 2 < KT) OG_ISSUE(kt + 2);

        const uint32_t Asm = sbase + (kt % 3) * 16384;
        const uint32_t Bsm = sbase + 49152 + (kt % 3) * 8192;

        #pragma unroll
        for (int kh = 0; kh < 2; kh++) {
            uint32_t bf[2][4];
            #pragma unroll
            for (int nt = 0; nt < 2; nt++)
                ldm_x4(Bsm + bRow[nt] + (((kh * 4 + sel) ^ swz) << 4), bf[nt]);
            #pragma unroll
            for (int kk2 = 0; kk2 < 2; kk2++) {
                const int kk = kh * 2 + kk2;
                uint32_t af[4][4];
                #pragma unroll
                for (int mt = 0; mt < 4; mt++)
                    ldm_x4(Asm + aRow[mt] + (((kk * 2 + selc) ^ swz) << 4), af[mt]);
                #pragma unroll
                for (int mt = 0; mt < 4; mt++)
                    #pragma unroll
                    for (int nt = 0; nt < 2; nt++)
                        mma8(acc[mt][nt], af[mt], &bf[nt][kk2 * 2]);
            }
        }
    }

    const int g = lane >> 2, t = lane & 3;
    const int bb = blockIdx.y * 2 + wm;
    float psum[2][2];
    #pragma unroll
    for (int nt = 0; nt < 2; nt++) {
        const int nl = wn * 16 + nt * 8 + 2 * t;
        const float2 cv = *(const float2*)(cs + (size_t)bb * DIMW + n0 + nl);
        const float add0 = sbo[nl] + cv.x;
        const float add1 = sbo[nl + 1] + cv.y;
        float s0 = 0.f, s1 = 0.f;
        #pragma unroll
        for (int mt = 0; mt < 4; mt++) {
            const int row0 = m0 + wm * 64 + mt * 16 + g;
            #pragma unroll
            for (int rh = 0; rh < 2; rh++) {
                const int row = row0 + rh * 8;
                float2 ov = make_float2(acc[mt][nt][rh * 2 + 0] + add0,
                                        acc[mt][nt][rh * 2 + 1] + add1);
                if (roundOut) { ov.x = tf32r(ov.x); ov.y = tf32r(ov.y); }
                *(float2*)(out + (size_t)row * DIMW + n0 + nl) = ov;
                s0 += ov.x; s1 += ov.y;
            }
        }
        psum[nt][0] = s0; psum[nt][1] = s1;
    }
    if (pooled) {
        #pragma unroll
        for (int nt = 0; nt < 2; nt++) {
            #pragma unroll
            for (int o = 4; o < 32; o <<= 1) {
                psum[nt][0] += __shfl_xor_sync(0xffffffffu, psum[nt][0], o);
                psum[nt][1] += __shfl_xor_sync(0xffffffffu, psum[nt][1], o);
            }
        }
        if (lane < 4) {
            #pragma unroll
            for (int nt = 0; nt < 2; nt++) {
                const int nl = wn * 16 + nt * 8 + 2 * lane;
                float2 pv = make_float2(psum[nt][0] * (1.f / (float)SEQ),
                                        psum[nt][1] * (1.f / (float)SEQ));
                *(float2*)(pooled + (size_t)bb * DIMW + n0 + nl) = pv;
            }
        }
    }
}

// ---------------------------------------------------------------------------
__global__ __launch_bounds__(256)
void scan_kernel(const float* __restrict__ decay, const float* __restrict__ drive,
                 float* __restrict__ hs, float* __restrict__ fin)
{
    const int b = blockIdx.x;
    const int n = threadIdx.x;
    size_t base = (size_t)b * SEQ * SDIMW + n;
    float h = 0.f;
    #pragma unroll 8
    for (int s = 0; s < SEQ; s++) {
        size_t idx = base + (size_t)s * SDIMW;
        h = fmaf(decay[idx], h, drive[idx]);
        hs[idx] = tf32r(h);
    }
    fin[b * SDIMW + n] = h;
}

// ---------------------------------------------------------------------------
// cstate v3 (R12-proven): 256 thr, CS_BG=4, n unrolled x8.
// ---------------------------------------------------------------------------
#define CS_BG 4
__global__ __launch_bounds__(256)
void cstate_kernel(const float* __restrict__ fin, const float* __restrict__ Ws,
                   const float* __restrict__ bs, float* __restrict__ cs)
{
    __shared__ float sf[CS_BG][SDIMW];
    const int d = blockIdx.x * 256 + threadIdx.x;
    const int b0 = blockIdx.y * CS_BG;
    {
        const int row = threadIdx.x >> 6, c4 = threadIdx.x & 63;
        *(float4*)&sf[row][c4 * 4] =
            *(const float4*)(fin + (size_t)(b0 + row) * SDIMW + c4 * 4);
    }
    __syncthreads();

    float acc[CS_BG] = {};
    #pragma unroll 4
    for (int n = 0; n < SDIMW; n += 8) {
        float w[8];
        #pragma unroll
        for (int j = 0; j < 8; j++)
            w[j] = Ws[(size_t)(n + j) * DIMW + d];
        #pragma unroll
        for (int b = 0; b < CS_BG; b++) {
            #pragma unroll
            for (int j = 0; j < 8; j++)
                acc[b] = fmaf(sf[b][n + j], w[j], acc[b]);
        }
    }
    const float bsv = bs[d];
    #pragma unroll
    for (int b = 0; b < CS_BG; b++)
        cs[(size_t)(b0 + b) * DIMW + d] = acc[b] + bsv;
}

// ---------------------------------------------------------------------------
__global__ __launch_bounds__(256)
void final_kernel(const float* __restrict__ pmean, const float* __restrict__ cs,
                  const float* __restrict__ gamma, const float* __restrict__ beta,
                  float* __restrict__ out)
{
    const int b = blockIdx.x;
    const int tid = threadIdx.x;

    float pooled[4];
    float lsum = 0.f, lsq = 0.f;
    #pragma unroll
    for (int i = 0; i < 4; i++) {
        const int d = i * 256 + tid;
        float p = cs[(size_t)b * DIMW + d] + pmean[(size_t)b * DIMW + d];
        pooled[i] = p;
        lsum += p;
        lsq  += p * p;
    }

    __shared__ float s1[8], s2[8];
    #pragma unroll
    for (int o = 16; o > 0; o >>= 1) {
        lsum += __shfl_xor_sync(0xffffffffu, lsum, o);
        lsq  += __shfl_xor_sync(0xffffffffu, lsq,  o);
    }
    if ((tid & 31) == 0) { s1[tid >> 5] = lsum; s2[tid >> 5] = lsq; }
    __syncthreads();
    float tsum = 0.f, tsq = 0.f;
    #pragma unroll
    for (int w = 0; w < 8; w++) { tsum += s1[w]; tsq += s2[w]; }

    const float mu  = tsum * (1.f / (float)DIMW);
    const float var = tsq * (1.f / (float)DIMW) - mu * mu;
    const float rstd = rsqrtf(var + EPS);

    #pragma unroll
    for (int i = 0; i < 4; i++) {
        const int d = i * 256 + tid;
        out[(size_t)b * DIMW + d] = (pooled[i] - mu) * rstd * gamma[d] + beta[d];
    }
}

// ---------------------------------------------------------------------------
extern "C" void kernel_launch(void* const* d_in, const int* in_sizes, int n_in,
                              void* d_out, int out_size)
{
    const float* X     = (const float*)d_in[0];
    const float* Wd    = (const float*)d_in[1];
    const float* bd    = (const float*)d_in[2];
    const float* Wi    = (const float*)d_in[3];
    const float* bi    = (const float*)d_in[4];
    const float* A_log = (const float*)d_in[5];
    const float* Wo    = (const float*)d_in[6];
    const float* bo    = (const float*)d_in[7];
    const float* Ws    = (const float*)d_in[8];
    const float* bs    = (const float*)d_in[9];
    const float* gamma = (const float*)d_in[10];
    const float* beta  = (const float*)d_in[11];

    float* out_repr   = (float*)d_out;                         // [B, D]
    float* out_hidden = (float*)d_out + (size_t)BATCH * DIMW;  // [B, S, D]

    float *p_decay, *p_drive, *p_hs, *p_hidden, *p_xr, *p_final, *p_cstate,
          *p_pooled, *p_wt;
    cudaGetSymbolAddress((void**)&p_decay,  g_decay);
    cudaGetSymbolAddress((void**)&p_drive,  g_drive);
    cudaGetSymbolAddress((void**)&p_hs,     g_hs);
    cudaGetSymbolAddress((void**)&p_hidden, g_hidden);
    cudaGetSymbolAddress((void**)&p_xr,     g_xr);
    cudaGetSymbolAddress((void**)&p_final,  g_final);
    cudaGetSymbolAddress((void**)&p_cstate, g_cstate);
    cudaGetSymbolAddress((void**)&p_pooled, g_pooled);
    cudaGetSymbolAddress((void**)&p_wt,     g_wt);

    cudaFuncSetAttribute(proj_mma_kernel,
                         cudaFuncAttributeMaxDynamicSharedMemorySize, PJ_SMEM);
    cudaFuncSetAttribute(outgemm_mma_kernel,
                         cudaFuncAttributeMaxDynamicSharedMemorySize, OG_SMEM);

    const size_t WSZ = (size_t)SDIMW * DIMW;
    float* WdT0 = p_wt + 0 * WSZ;
    float* WiT0 = p_wt + 1 * WSZ;
    float* WoT0 = p_wt + 2 * WSZ;
    float* WdT1 = p_wt + 3 * WSZ;
    float* WiT1 = p_wt + 4 * WSZ;
    float* WoT1 = p_wt + 5 * WSZ;

    transpose6_kernel<<<dim3(8, 32, 6), dim3(32, 8)>>>(Wd, Wi, Wo, p_wt);
    round_kernel<<<(MROWS * DIMW) / (256 * 4), 256>>>((const float4*)X,
                                                      (float4*)p_xr);

    const dim3 pjGrid(SDIMW / 32, MROWS / 128);    // (8, 128)
    const dim3 ogGrid(DIMW / 64, MROWS / 128);     // (16, 128)
    const dim3 csGrid(DIMW / 256, BATCH / CS_BG);  // (4, 64)

    // ---------------- layer 0 ----------------
    proj_mma_kernel<<<pjGrid, 256, PJ_SMEM>>>(p_xr, WdT0, WiT0, bd, bi, A_log,
                                              p_decay, p_drive);
    scan_kernel<<<BATCH, 256>>>(p_decay, p_drive, p_hs, p_final);
    cstate_kernel<<<csGrid, 256>>>(p_final, Ws, bs, p_cstate);
    outgemm_mma_kernel<<<ogGrid, 256, OG_SMEM>>>(p_hs, WoT0, bo, p_cstate,
                                                 p_hidden, nullptr, 1);

    // ---------------- layer 1 (hidden already tf32-rounded) ----------------
    proj_mma_kernel<<<pjGrid, 256, PJ_SMEM>>>(p_hidden, WdT1, WiT1, bd + SDIMW,
                                              bi + SDIMW, A_log + SDIMW,
                                              p_decay, p_drive);
    scan_kernel<<<BATCH, 256>>>(p_decay, p_drive, p_hs, p_final);
    cstate_kernel<<<csGrid, 256>>>(p_final, Ws + WSZ, bs + DIMW, p_cstate);
    outgemm_mma_kernel<<<ogGrid, 256, OG_SMEM>>>(p_hs, WoT1, bo + DIMW, p_cstate,
                                                 out_hidden, p_pooled, 0);

    // ---------------- LayerNorm ----------------
    final_kernel<<<BATCH, 256>>>(p_pooled, p_cstate, gamma, beta, out_repr);
}

// round 17
// speedup vs baseline: 1.1944x; 1.0315x over previous
#include <cuda_runtime.h>
#include <cstdint>

#define BATCH 256
#define SEQ   64
#define DIMW  1024
#define SDIMW 256
#define MROWS (BATCH*SEQ)   // 16384
#define EPS   1e-5f

// ---------------- scratch (static device globals; no runtime allocation) ----
__device__ float g_hs   [MROWS * SDIMW];
__device__ float g_hidden[(size_t)MROWS * DIMW];  // layer-0 hidden (tf32-rounded)
__device__ float g_xr    [(size_t)MROWS * DIMW];  // tf32-rounded X
__device__ float g_final [BATCH * SDIMW];
__device__ float g_cstate[BATCH * DIMW];
__device__ float g_pooled[BATCH * DIMW];
__device__ float g_wt[6 * SDIMW * DIMW];   // transposed + tf32-rounded weights

__device__ __forceinline__ float softplusf(float x) {
    float e = __expf(-fabsf(x));
    return fmaxf(x, 0.f) + __logf(1.f + e);
}
__device__ __forceinline__ float tf32r(float f) {
    uint32_t r;
    asm("cvt.rna.tf32.f32 %0, %1;" : "=r"(r) : "f"(f));
    return __uint_as_float(r);
}
__device__ __forceinline__ float4 tf32r4(float4 v) {
    return make_float4(tf32r(v.x), tf32r(v.y), tf32r(v.z), tf32r(v.w));
}
__device__ __forceinline__ uint32_t smem_u32(const void* p) {
    uint32_t a;
    asm("{ .reg .u64 t; cvta.to.shared.u64 t, %1; cvt.u32.u64 %0, t; }"
        : "=r"(a) : "l"(p));
    return a;
}
__device__ __forceinline__ void ldm_x4(uint32_t addr, uint32_t* r) {
    asm volatile("ldmatrix.sync.aligned.m8n8.x4.shared.b16 {%0,%1,%2,%3}, [%4];"
                 : "=r"(r[0]), "=r"(r[1]), "=r"(r[2]), "=r"(r[3]) : "r"(addr));
}
__device__ __forceinline__ void mma8(float* c, const uint32_t* a, const uint32_t* b) {
    asm volatile("mma.sync.aligned.m16n8k8.row.col.f32.tf32.tf32.f32 "
                 "{%0,%1,%2,%3}, {%4,%5,%6,%7}, {%8,%9}, {%0,%1,%2,%3};"
                 : "+f"(c[0]), "+f"(c[1]), "+f"(c[2]), "+f"(c[3])
                 : "r"(a[0]), "r"(a[1]), "r"(a[2]), "r"(a[3]),
                   "r"(b[0]), "r"(b[1]));
}
__device__ __forceinline__ void cp16(uint32_t dst, const void* src) {
    asm volatile("cp.async.cg.shared.global [%0], [%1], 16;"
                 :: "r"(dst), "l"(src) : "memory");
}
__device__ __forceinline__ void cp_commit() {
    asm volatile("cp.async.commit_group;" ::: "memory");
}

// ---------------------------------------------------------------------------
// prep: z=0..5 -> weight transposes (+tf32 round); z=6..21 -> X rounding.
// block (32, 8). For z>=6: bid = (z-6)*256 + by*8 + bx handles 1024 float4.
// ---------------------------------------------------------------------------
__global__ void prep_kernel(const float* __restrict__ Wd,
                            const float* __restrict__ Wi,
                            const float* __restrict__ Wo,
                            float* __restrict__ wt,
                            const float4* __restrict__ X4,
                            float4* __restrict__ Xr4) {
    const int z = blockIdx.z;
    const int tx = threadIdx.x, ty = threadIdx.y;
    if (z >= 6) {
        const size_t bid = (size_t)(z - 6) * 256 + blockIdx.y * 8 + blockIdx.x;
        const size_t base = bid * 1024 + ty * 32 + tx;
        #pragma unroll
        for (int i = 0; i < 4; i++)
            Xr4[base + i * 256] = tf32r4(X4[base + i * 256]);
        return;
    }
    __shared__ float t[32][33];
    const int layer = z / 3, mat = z % 3;
    const size_t WSZ = (size_t)SDIMW * DIMW;
    const float* src = (mat == 0 ? Wd : (mat == 1 ? Wi : Wo)) + layer * WSZ;
    float* dst = wt + (size_t)z * WSZ;
    int R, C, c0, r0;
    if (mat == 2) { R = SDIMW; C = DIMW; c0 = blockIdx.y * 32; r0 = blockIdx.x * 32; }
    else          { R = DIMW; C = SDIMW; c0 = blockIdx.x * 32; r0 = blockIdx.y * 32; }
    #pragma unroll
    for (int k = 0; k < 4; k++)
        t[ty + 8 * k][tx] = src[(size_t)(r0 + ty + 8 * k) * C + c0 + tx];
    __syncthreads();
    #pragma unroll
    for (int k = 0; k < 4; k++)
        dst[(size_t)(c0 + ty + 8 * k) * R + r0 + tx] = tf32r(t[tx][ty + 8 * k]);
}

// ---------------------------------------------------------------------------
// proj v4 = R16 proj v3 + fused scan epilogue.
// CTA 128m x 32n(dual), 8 warps 4m x 2n, 2 CTAs/SM, cp.async 3-stage.
// Epilogue: gates -> smem (stride-34 rows, reusing stage buffers), then
// 64 threads scan S=64 and write hs (tf32-rounded) + fin. Bit-identical
// to the unfused R16 path (smem f32 staging is exact).
// smem: stages @0..73728 (reused by sdec@0, sdrv@17408), biases @73728.
// ---------------------------------------------------------------------------
#define PJ_SMEM (73728 + 3 * 32 * 4)
__global__ __launch_bounds__(256, 2)
void proj_mma_kernel(const float* __restrict__ X,
                     const float* __restrict__ WdT, const float* __restrict__ WiT,
                     const float* __restrict__ bd, const float* __restrict__ bi,
                     const float* __restrict__ A_log,
                     float* __restrict__ hs, float* __restrict__ fin)
{
    extern __shared__ char smem[];
    const uint32_t sbase = smem_u32(smem);
    const int tid = threadIdx.x, wid = tid >> 5, lane = tid & 31;
    const int wm = wid & 3, wn = wid >> 2;     // 4m x 2n warp grid
    const int m0 = blockIdx.y * 128, n0 = blockIdx.x * 32;

    float* sbd = (float*)(smem + 73728);
    float* sbi = sbd + 32;
    float* ssa = sbi + 32;
    if (tid < 32) {
        sbd[tid] = bd[n0 + tid];
        sbi[tid] = bi[n0 + tid];
        ssa[tid] = softplusf(A_log[n0 + tid]);
    }

    const int lrow4 = tid >> 3, lc16 = tid & 7;   // lrow4: 0..31
    const int swz = lane & 7, sel = lane >> 3;
    const int selr = (sel & 1) * 8, selc = sel >> 1;

    uint32_t aRow[2], bRow[2];
    #pragma unroll
    for (int mt = 0; mt < 2; mt++)
        aRow[mt] = (uint32_t)((wm * 32 + mt * 16 + selr + swz) * 128);
    #pragma unroll
    for (int nt = 0; nt < 2; nt++)
        bRow[nt] = (uint32_t)((wn * 16 + nt * 8 + swz) * 128);

    const uint32_t ldOffA[4] = {
        (uint32_t)((lrow4 + 0)  * 128 + ((lc16 ^ ((lrow4 + 0)  & 7)) << 4)),
        (uint32_t)((lrow4 + 32) * 128 + ((lc16 ^ ((lrow4 + 32) & 7)) << 4)),
        (uint32_t)((lrow4 + 64) * 128 + ((lc16 ^ ((lrow4 + 64) & 7)) << 4)),
        (uint32_t)((lrow4 + 96) * 128 + ((lc16 ^ ((lrow4 + 96) & 7)) << 4))
    };
    const float* aSrc = X   + (size_t)(m0 + lrow4) * DIMW + lc16 * 4;
    const float* dSrc = WdT + (size_t)(n0 + lrow4) * DIMW + lc16 * 4;
    const float* iSrc = WiT + (size_t)(n0 + lrow4) * DIMW + lc16 * 4;

    #define PJ_ISSUE(kt_) do {                                                  \
        const int _s = (kt_) % 3;                                               \
        const int _k0 = (kt_) * 32;                                             \
        _Pragma("unroll")                                                       \
        for (int i = 0; i < 4; i++)                                             \
            cp16(sbase + _s * 16384 + ldOffA[i],                                \
                 aSrc + (size_t)(i * 32) * DIMW + _k0);                         \
        cp16(sbase + 49152 + _s * 4096 + ldOffA[0], dSrc + _k0);                \
        cp16(sbase + 61440 + _s * 4096 + ldOffA[0], iSrc + _k0);                \
        cp_commit();                                                            \
    } while (0)

    PJ_ISSUE(0);
    PJ_ISSUE(1);

    float accD[2][2][4] = {};
    float accI[2][2][4] = {};

    const int KT = DIMW / 32;   // 32
    for (int kt = 0; kt < KT; kt++) {
        if (kt == KT - 1)
            asm volatile("cp.async.wait_group 0;" ::: "memory");
        else
            asm volatile("cp.async.wait_group 1;" ::: "memory");
        __syncthreads();
        if (kt + 2 < KT) PJ_ISSUE(kt + 2);

        const uint32_t Asm  = sbase + (kt % 3) * 16384;
        const uint32_t Bdsm = sbase + 49152 + (kt % 3) * 4096;
        const uint32_t Bism = sbase + 61440 + (kt % 3) * 4096;

        uint32_t af[2][4][4];
        #pragma unroll
        for (int mt = 0; mt < 2; mt++)
            #pragma unroll
            for (int kk = 0; kk < 4; kk++)
                ldm_x4(Asm + aRow[mt] + (((kk * 2 + selc) ^ swz) << 4), af[mt][kk]);

        #pragma unroll
        for (int out = 0; out < 2; out++) {
            const uint32_t Bsm = out ? Bism : Bdsm;
            #pragma unroll
            for (int kh = 0; kh < 2; kh++) {
                uint32_t bf[2][4];
                #pragma unroll
                for (int nt = 0; nt < 2; nt++)
                    ldm_x4(Bsm + bRow[nt] + (((kh * 4 + sel) ^ swz) << 4), bf[nt]);
                #pragma unroll
                for (int kk2 = 0; kk2 < 2; kk2++)
                    #pragma unroll
                    for (int mt = 0; mt < 2; mt++)
                        #pragma unroll
                        for (int nt = 0; nt < 2; nt++)
                            mma8(out ? accI[mt][nt] : accD[mt][nt],
                                 af[mt][kh * 2 + kk2], &bf[nt][kk2 * 2]);
            }
        }
    }

    // ---- gate epilogue into smem (reuse stage buffers; all reads done) ----
    __syncthreads();
    float* sdec = (float*)smem;                // 128 x 34 floats (17408 B)
    float* sdrv = (float*)(smem + 17408);      // 128 x 34 floats
    const int g = lane >> 2, t = lane & 3;
    #pragma unroll
    for (int mt = 0; mt < 2; mt++) {
        const int row0 = wm * 32 + mt * 16 + g;
        #pragma unroll
        for (int nt = 0; nt < 2; nt++) {
            const int nl = wn * 16 + nt * 8 + 2 * t;
            const float b0 = sbd[nl], b1 = sbd[nl + 1];
            const float i0 = sbi[nl], i1 = sbi[nl + 1];
            const float a0 = ssa[nl], a1 = ssa[nl + 1];
            #pragma unroll
            for (int rh = 0; rh < 2; rh++) {
                const int row = row0 + rh * 8;
                const float de0 = softplusf(accD[mt][nt][rh * 2 + 0] + b0);
                const float de1 = softplusf(accD[mt][nt][rh * 2 + 1] + b1);
                float2 dec = make_float2(__expf(-de0 * a0), __expf(-de1 * a1));
                float2 drv = make_float2(de0 * (accI[mt][nt][rh * 2 + 0] + i0),
                                         de1 * (accI[mt][nt][rh * 2 + 1] + i1));
                *(float2*)&sdec[row * 34 + nl] = dec;
                *(float2*)&sdrv[row * 34 + nl] = drv;
            }
        }
    }
    __syncthreads();

    // ---- fused scan: 64 threads = (b in 0..1) x (n in 0..31) ----
    if (tid < 64) {
        const int b = tid >> 5, n = tid & 31;
        const int gb = blockIdx.y * 2 + b;
        const size_t hbase = (size_t)(m0 + b * 64) * SDIMW + n0 + n;
        float h = 0.f;
        #pragma unroll 8
        for (int s = 0; s < SEQ; s++) {
            const int row = b * 64 + s;
            h = fmaf(sdec[row * 34 + n], h, sdrv[row * 34 + n]);
            hs[hbase + (size_t)s * SDIMW] = tf32r(h);
        }
        fin[gb * SDIMW + n0 + n] = h;
    }
}

// ---------------------------------------------------------------------------
// outgemm v2 (R13-proven): CTA 128m x 64n, warp 64m x 16n, 2 CTAs/SM.
// ---------------------------------------------------------------------------
#define OG_SMEM (73728 + 64 * 4)
__global__ __launch_bounds__(256, 2)
void outgemm_mma_kernel(const float* __restrict__ HS, const float* __restrict__ WoT,
                        const float* __restrict__ bo, const float* __restrict__ cs,
                        float* __restrict__ out, float* __restrict__ pooled,
                        int roundOut)
{
    extern __shared__ char smem[];
    const uint32_t sbase = smem_u32(smem);
    const int tid = threadIdx.x, wid = tid >> 5, lane = tid & 31;
    const int wm = wid & 1, wn = wid >> 1;
    const int m0 = blockIdx.y * 128, n0 = blockIdx.x * 64;

    float* sbo = (float*)(smem + 73728);
    if (tid < 64) sbo[tid] = bo[n0 + tid];

    const int lrow4 = tid >> 3, lc16 = tid & 7;
    const int swz = lane & 7, sel = lane >> 3;
    const int selr = (sel & 1) * 8, selc = sel >> 1;

    uint32_t aRow[4], bRow[2];
    #pragma unroll
    for (int mt = 0; mt < 4; mt++)
        aRow[mt] = (uint32_t)((wm * 64 + mt * 16 + selr + swz) * 128);
    #pragma unroll
    for (int nt = 0; nt < 2; nt++)
        bRow[nt] = (uint32_t)((wn * 16 + nt * 8 + swz) * 128);

    const uint32_t ldOff[4] = {
        (uint32_t)((lrow4 + 0)  * 128 + ((lc16 ^ ((lrow4 + 0)  & 7)) << 4)),
        (uint32_t)((lrow4 + 32) * 128 + ((lc16 ^ ((lrow4 + 32) & 7)) << 4)),
        (uint32_t)((lrow4 + 64) * 128 + ((lc16 ^ ((lrow4 + 64) & 7)) << 4)),
        (uint32_t)((lrow4 + 96) * 128 + ((lc16 ^ ((lrow4 + 96) & 7)) << 4))
    };
    const float* aSrc = HS  + (size_t)(m0 + lrow4) * SDIMW + lc16 * 4;
    const float* bSrc = WoT + (size_t)(n0 + lrow4) * SDIMW + lc16 * 4;

    #define OG_ISSUE(kt_) do {                                                  \
        const int _s = (kt_) % 3;                                               \
        const int _k0 = (kt_) * 32;                                             \
        _Pragma("unroll")                                                       \
        for (int i = 0; i < 4; i++)                                             \
            cp16(sbase + _s * 16384 + ldOff[i],                                 \
                 aSrc + (size_t)(i * 32) * SDIMW + _k0);                        \
        _Pragma("unroll")                                                       \
        for (int i = 0; i < 2; i++)                                             \
            cp16(sbase + 49152 + _s * 8192 + ldOff[i],                          \
                 bSrc + (size_t)(i * 32) * SDIMW + _k0);                        \
        cp_commit();                                                            \
    } while (0)

    OG_ISSUE(0);
    OG_ISSUE(1);

    float acc[4][2][4] = {};

    const int KT = SDIMW / 32;   // 8
    for (int kt = 0; kt < KT; kt++) {
        if (kt == KT - 1)
            asm volatile("cp.async.wait_group 0;" ::: "memory");
        else
            asm volatile("cp.async.wait_group 1;" ::: "memory");
        __syncthreads();
        if (kt + 2 < KT) OG_ISSUE(kt + 2);

        const uint32_t Asm = sbase + (kt % 3) * 16384;
        const uint32_t Bsm = sbase + 49152 + (kt % 3) * 8192;

        #pragma unroll
        for (int kh = 0; kh < 2; kh++) {
            uint32_t bf[2][4];
            #pragma unroll
            for (int nt = 0; nt < 2; nt++)
                ldm_x4(Bsm + bRow[nt] + (((kh * 4 + sel) ^ swz) << 4), bf[nt]);
            #pragma unroll
            for (int kk2 = 0; kk2 < 2; kk2++) {
                const int kk = kh * 2 + kk2;
                uint32_t af[4][4];
                #pragma unroll
                for (int mt = 0; mt < 4; mt++)
                    ldm_x4(Asm + aRow[mt] + (((kk * 2 + selc) ^ swz) << 4), af[mt]);
                #pragma unroll
                for (int mt = 0; mt < 4; mt++)
                    #pragma unroll
                    for (int nt = 0; nt < 2; nt++)
                        mma8(acc[mt][nt], af[mt], &bf[nt][kk2 * 2]);
            }
        }
    }

    const int g = lane >> 2, t = lane & 3;
    const int bb = blockIdx.y * 2 + wm;
    float psum[2][2];
    #pragma unroll
    for (int nt = 0; nt < 2; nt++) {
        const int nl = wn * 16 + nt * 8 + 2 * t;
        const float2 cv = *(const float2*)(cs + (size_t)bb * DIMW + n0 + nl);
        const float add0 = sbo[nl] + cv.x;
        const float add1 = sbo[nl + 1] + cv.y;
        float s0 = 0.f, s1 = 0.f;
        #pragma unroll
        for (int mt = 0; mt < 4; mt++) {
            const int row0 = m0 + wm * 64 + mt * 16 + g;
            #pragma unroll
            for (int rh = 0; rh < 2; rh++) {
                const int row = row0 + rh * 8;
                float2 ov = make_float2(acc[mt][nt][rh * 2 + 0] + add0,
                                        acc[mt][nt][rh * 2 + 1] + add1);
                if (roundOut) { ov.x = tf32r(ov.x); ov.y = tf32r(ov.y); }
                *(float2*)(out + (size_t)row * DIMW + n0 + nl) = ov;
                s0 += ov.x; s1 += ov.y;
            }
        }
        psum[nt][0] = s0; psum[nt][1] = s1;
    }
    if (pooled) {
        #pragma unroll
        for (int nt = 0; nt < 2; nt++) {
            #pragma unroll
            for (int o = 4; o < 32; o <<= 1) {
                psum[nt][0] += __shfl_xor_sync(0xffffffffu, psum[nt][0], o);
                psum[nt][1] += __shfl_xor_sync(0xffffffffu, psum[nt][1], o);
            }
        }
        if (lane < 4) {
            #pragma unroll
            for (int nt = 0; nt < 2; nt++) {
                const int nl = wn * 16 + nt * 8 + 2 * lane;
                float2 pv = make_float2(psum[nt][0] * (1.f / (float)SEQ),
                                        psum[nt][1] * (1.f / (float)SEQ));
                *(float2*)(pooled + (size_t)bb * DIMW + n0 + nl) = pv;
            }
        }
    }
}

// ---------------------------------------------------------------------------
// cstate v3 (R12-proven): 256 thr, CS_BG=4, n unrolled x8.
// ---------------------------------------------------------------------------
#define CS_BG 4
__global__ __launch_bounds__(256)
void cstate_kernel(const float* __restrict__ fin, const float* __restrict__ Ws,
                   const float* __restrict__ bs, float* __restrict__ cs)
{
    __shared__ float sf[CS_BG][SDIMW];
    const int d = blockIdx.x * 256 + threadIdx.x;
    const int b0 = blockIdx.y * CS_BG;
    {
        const int row = threadIdx.x >> 6, c4 = threadIdx.x & 63;
        *(float4*)&sf[row][c4 * 4] =
            *(const float4*)(fin + (size_t)(b0 + row) * SDIMW + c4 * 4);
    }
    __syncthreads();

    float acc[CS_BG] = {};
    #pragma unroll 4
    for (int n = 0; n < SDIMW; n += 8) {
        float w[8];
        #pragma unroll
        for (int j = 0; j < 8; j++)
            w[j] = Ws[(size_t)(n + j) * DIMW + d];
        #pragma unroll
        for (int b = 0; b < CS_BG; b++) {
            #pragma unroll
            for (int j = 0; j < 8; j++)
                acc[b] = fmaf(sf[b][n + j], w[j], acc[b]);
        }
    }
    const float bsv = bs[d];
    #pragma unroll
    for (int b = 0; b < CS_BG; b++)
        cs[(size_t)(b0 + b) * DIMW + d] = acc[b] + bsv;
}

// ---------------------------------------------------------------------------
__global__ __launch_bounds__(256)
void final_kernel(const float* __restrict__ pmean, const float* __restrict__ cs,
                  const float* __restrict__ gamma, const float* __restrict__ beta,
                  float* __restrict__ out)
{
    const int b = blockIdx.x;
    const int tid = threadIdx.x;

    float pooled[4];
    float lsum = 0.f, lsq = 0.f;
    #pragma unroll
    for (int i = 0; i < 4; i++) {
        const int d = i * 256 + tid;
        float p = cs[(size_t)b * DIMW + d] + pmean[(size_t)b * DIMW + d];
        pooled[i] = p;
        lsum += p;
        lsq  += p * p;
    }

    __shared__ float s1[8], s2[8];
    #pragma unroll
    for (int o = 16; o > 0; o >>= 1) {
        lsum += __shfl_xor_sync(0xffffffffu, lsum, o);
        lsq  += __shfl_xor_sync(0xffffffffu, lsq,  o);
    }
    if ((tid & 31) == 0) { s1[tid >> 5] = lsum; s2[tid >> 5] = lsq; }
    __syncthreads();
    float tsum = 0.f, tsq = 0.f;
    #pragma unroll
    for (int w = 0; w < 8; w++) { tsum += s1[w]; tsq += s2[w]; }

    const float mu  = tsum * (1.f / (float)DIMW);
    const float var = tsq * (1.f / (float)DIMW) - mu * mu;
    const float rstd = rsqrtf(var + EPS);

    #pragma unroll
    for (int i = 0; i < 4; i++) {
        const int d = i * 256 + tid;
        out[(size_t)b * DIMW + d] = (pooled[i] - mu) * rstd * gamma[d] + beta[d];
    }
}

// ---------------------------------------------------------------------------
extern "C" void kernel_launch(void* const* d_in, const int* in_sizes, int n_in,
                              void* d_out, int out_size)
{
    const float* X     = (const float*)d_in[0];
    const float* Wd    = (const float*)d_in[1];
    const float* bd    = (const float*)d_in[2];
    const float* Wi    = (const float*)d_in[3];
    const float* bi    = (const float*)d_in[4];
    const float* A_log = (const float*)d_in[5];
    const float* Wo    = (const float*)d_in[6];
    const float* bo    = (const float*)d_in[7];
    const float* Ws    = (const float*)d_in[8];
    const float* bs    = (const float*)d_in[9];
    const float* gamma = (const float*)d_in[10];
    const float* beta  = (const float*)d_in[11];

    float* out_repr   = (float*)d_out;                         // [B, D]
    float* out_hidden = (float*)d_out + (size_t)BATCH * DIMW;  // [B, S, D]

    float *p_hs, *p_hidden, *p_xr, *p_final, *p_cstate, *p_pooled, *p_wt;
    cudaGetSymbolAddress((void**)&p_hs,     g_hs);
    cudaGetSymbolAddress((void**)&p_hidden, g_hidden);
    cudaGetSymbolAddress((void**)&p_xr,     g_xr);
    cudaGetSymbolAddress((void**)&p_final,  g_final);
    cudaGetSymbolAddress((void**)&p_cstate, g_cstate);
    cudaGetSymbolAddress((void**)&p_pooled, g_pooled);
    cudaGetSymbolAddress((void**)&p_wt,     g_wt);

    cudaFuncSetAttribute(proj_mma_kernel,
                         cudaFuncAttributeMaxDynamicSharedMemorySize, PJ_SMEM);
    cudaFuncSetAttribute(outgemm_mma_kernel,
                         cudaFuncAttributeMaxDynamicSharedMemorySize, OG_SMEM);

    const size_t WSZ = (size_t)SDIMW * DIMW;
    float* WdT0 = p_wt + 0 * WSZ;
    float* WiT0 = p_wt + 1 * WSZ;
    float* WoT0 = p_wt + 2 * WSZ;
    float* WdT1 = p_wt + 3 * WSZ;
    float* WiT1 = p_wt + 4 * WSZ;
    float* WoT1 = p_wt + 5 * WSZ;

    // prep: 6 transposes + X rounding in ONE launch.
    // z 0..5: transposes (8x32 blocks); z 6..21: rounding (16 slices x 256
    // blocks x 1024 float4 = 4,194,304 float4 = 16.8M floats) ✓
    prep_kernel<<<dim3(8, 32, 22), dim3(32, 8)>>>(Wd, Wi, Wo, p_wt,
                                                  (const float4*)X, (float4*)p_xr);

    const dim3 pjGrid(SDIMW / 32, MROWS / 128);    // (8, 128)
    const dim3 ogGrid(DIMW / 64, MROWS / 128);     // (16, 128)
    const dim3 csGrid(DIMW / 256, BATCH / CS_BG);  // (4, 64)

    // ---------------- layer 0 (proj+scan fused) ----------------
    proj_mma_kernel<<<pjGrid, 256, PJ_SMEM>>>(p_xr, WdT0, WiT0, bd, bi, A_log,
                                              p_hs, p_final);
    cstate_kernel<<<csGrid, 256>>>(p_final, Ws, bs, p_cstate);
    outgemm_mma_kernel<<<ogGrid, 256, OG_SMEM>>>(p_hs, WoT0, bo, p_cstate,
                                                 p_hidden, nullptr, 1);

    // ---------------- layer 1 (hidden already tf32-rounded) ----------------
    proj_mma_kernel<<<pjGrid, 256, PJ_SMEM>>>(p_hidden, WdT1, WiT1, bd + SDIMW,
                                              bi + SDIMW, A_log + SDIMW,
                                              p_hs, p_final);
    cstate_kernel<<<csGrid, 256>>>(p_final, Ws + WSZ, bs + DIMW, p_cstate);
    outgemm_mma_kernel<<<ogGrid, 256, OG_SMEM>>>(p_hs, WoT1, bo + DIMW, p_cstate,
                                                 out_hidden, p_pooled, 0);

    // ---------------- LayerNorm ----------------
    final_kernel<<<BATCH, 256>>>(p_pooled, p_cstate, gamma, beta, out_repr);
}